// round 1
// baseline (speedup 1.0000x reference)
#include <cuda_runtime.h>
#include <cuda_fp16.h>
#include <math.h>
#include <stdint.h>

#define TDIM 512
#define TOUT 1024
#define TBATCH 65536

// Scratch: W converted to fp16 (1 MB) + inv_freq table. __device__ globals are
// the sanctioned scratch mechanism (no allocation allowed).
__device__ __half g_W16[TOUT * TDIM];
__device__ float  g_invf[TDIM];

// ---------------------------------------------------------------------------
// Prep kernel: convert W fp32 -> fp16, compute inv_freq exactly as reference:
// xf = fp32(-(2i/512) * fp32(log(1e4))), invf = exp(xf) (double, then to f32).
// ---------------------------------------------------------------------------
__global__ void prep_kernel(const float* __restrict__ W) {
    int idx = blockIdx.x * blockDim.x + threadIdx.x;
    if (idx < TOUT * TDIM)
        g_W16[idx] = __float2half_rn(W[idx]);
    if (idx < TDIM) {
        float a  = (2.0f * (float)idx) / 512.0f;          // exact in fp32
        float xf = __fmul_rn(a, 9.210340371976184f);      // one fp32 rounding, like ref
        g_invf[idx] = (float)exp(-(double)xf);            // correctly-rounded exp
    }
}

// ---------------------------------------------------------------------------
// Accurate sin/cos for args up to ~1024 rad (Juffa 3-constant Cody-Waite
// reduction + degree-9/8 polynomials). odd=0 -> sin(x), odd=1 -> cos(x).
// ---------------------------------------------------------------------------
__device__ __forceinline__ float sincos_sel(float x, int odd) {
    float j  = __fmaf_rn(x, 0.63661977236758134f, 12582912.0f); // round(x*2/pi) via magic
    int   qi = __float_as_int(j);          // low bits hold the integer (x >= 0)
    float jf = __fadd_rn(j, -12582912.0f);
    float r  = __fmaf_rn(jf, -1.57079601e+00f, x);
    r        = __fmaf_rn(jf, -3.13916473e-07f, r);
    r        = __fmaf_rn(jf, -5.39030253e-15f, r);
    float r2 = __fmul_rn(r, r);
    // sin poly on |r| <= ~pi/4
    float ps = __fmaf_rn(2.75573192e-6f, r2, -1.98412698e-4f);
    ps = __fmaf_rn(ps, r2, 8.33333333e-3f);
    ps = __fmaf_rn(ps, r2, -1.66666667e-1f);
    float sp = __fmaf_rn(ps * r2, r, r);
    // cos poly
    float pc = __fmaf_rn(2.48015873e-5f, r2, -1.38888889e-3f);
    pc = __fmaf_rn(pc, r2, 4.16666667e-2f);
    pc = __fmaf_rn(pc, r2, -5.0e-1f);
    float cp = __fmaf_rn(pc, r2, 1.0f);
    int qq = qi + odd;                     // cos(x) = sin(x + pi/2)
    float v = (qq & 1) ? cp : sp;
    return (qq & 2) ? -v : v;
}

// ---------------------------------------------------------------------------
// Main fused kernel.
// Grid: 512 CTAs, each owns 128 batch rows. 512 threads = 16 warps (4M x 4N).
// SMEM: A = emb fp16 [128 x 512] swizzled (128 KB) at offset 0
//       W tiles: 2 x [256 x 64] fp16 swizzled (2 x 32 KB) at offset 131072
// N processed in 4 chunks of 256; K in 8 steps of 64, double-buffered.
// ---------------------------------------------------------------------------
__global__ void __launch_bounds__(512, 1) temb_main(
    const float* __restrict__ T,
    const float* __restrict__ bias,
    float* __restrict__ out)
{
    extern __shared__ char smem[];
    const int tid = threadIdx.x;
    const int mbase = blockIdx.x * 128;
    const uint32_t sbase = (uint32_t)__cvta_generic_to_shared(smem);

    // ---- Phase 1: compute embedding -> swizzled fp16 smem ----
    for (int p = tid; p < 128 * 256; p += 512) {
        int row = p >> 8;
        int c2  = (p & 255) * 2;
        float t  = __ldg(&T[mbase + row]);
        float e0 = sincos_sel(__fmul_rn(t, g_invf[c2]), 0);
        float e1 = sincos_sel(__fmul_rn(t, g_invf[c2 + 1]), 1);
        __half2 h = __floats2half2_rn(e0, e1);
        int u = c2 >> 3;  // 16B unit within row
        *(__half2*)(smem + row * 1024 + ((u ^ (row & 7)) << 4) + ((c2 & 7) << 1)) = h;
    }
    __syncthreads();

    const int lane = tid & 31;
    const int w    = tid >> 5;
    const int mw   = (w >> 2) * 32;  // warp M offset (0..96)
    const int nw   = (w & 3) * 64;   // warp N offset within 256-chunk

    // ldmatrix lane geometry
    const int arow0 = mw + ((lane >> 3) & 1) * 8 + (lane & 7);
    const int a_c8  = lane >> 4;                   // k unit offset 0/1
    const int bn0   = (lane & 7) + ((lane >> 4) << 3); // 0..15
    const int b_k8  = (lane >> 3) & 1;

    float acc[2][8][4];

    for (int nb = 0; nb < 4; nb++) {
        const int nchunk = nb * 256;
        #pragma unroll
        for (int mt = 0; mt < 2; mt++)
            #pragma unroll
            for (int nt = 0; nt < 8; nt++) {
                acc[mt][nt][0] = 0.f; acc[mt][nt][1] = 0.f;
                acc[mt][nt][2] = 0.f; acc[mt][nt][3] = 0.f;
            }

        uint4 wreg[4];
        // prologue: load k-tile 0 into buffer 0
        #pragma unroll
        for (int cc = 0; cc < 4; cc++) {
            int c = cc * 512 + tid;
            int n = c >> 3, u = c & 7;
            wreg[cc] = *(const uint4*)(g_W16 + (size_t)(nchunk + n) * 512 + u * 8);
        }
        #pragma unroll
        for (int cc = 0; cc < 4; cc++) {
            int c = cc * 512 + tid;
            int n = c >> 3, u = c & 7;
            *(uint4*)(smem + 131072 + n * 128 + ((u ^ (n & 7)) << 4)) = wreg[cc];
        }
        __syncthreads();

        for (int kt = 0; kt < 8; kt++) {
            const int cur = kt & 1;
            if (kt < 7) {
                #pragma unroll
                for (int cc = 0; cc < 4; cc++) {
                    int c = cc * 512 + tid;
                    int n = c >> 3, u = c & 7;
                    wreg[cc] = *(const uint4*)(g_W16 + (size_t)(nchunk + n) * 512
                                               + (kt + 1) * 64 + u * 8);
                }
            }
            const uint32_t wsm = sbase + 131072u + (cur ? 32768u : 0u);
            #pragma unroll
            for (int kk = 0; kk < 4; kk++) {
                uint32_t a[2][4];
                #pragma unroll
                for (int mt = 0; mt < 2; mt++) {
                    int row = arow0 + mt * 16;
                    int u = kt * 8 + kk * 2 + a_c8;
                    uint32_t addr = sbase + row * 1024 + ((u ^ (row & 7)) << 4);
                    asm volatile(
                        "ldmatrix.sync.aligned.m8n8.x4.shared.b16 {%0,%1,%2,%3}, [%4];"
                        : "=r"(a[mt][0]), "=r"(a[mt][1]), "=r"(a[mt][2]), "=r"(a[mt][3])
                        : "r"(addr));
                }
                #pragma unroll
                for (int j = 0; j < 4; j++) {
                    uint32_t b0, b1, b2, b3;
                    int n = nw + j * 16 + bn0;
                    int u = kk * 2 + b_k8;
                    uint32_t addr = wsm + n * 128 + ((u ^ (n & 7)) << 4);
                    asm volatile(
                        "ldmatrix.sync.aligned.m8n8.x4.shared.b16 {%0,%1,%2,%3}, [%4];"
                        : "=r"(b0), "=r"(b1), "=r"(b2), "=r"(b3) : "r"(addr));
                    #pragma unroll
                    for (int mt = 0; mt < 2; mt++) {
                        asm volatile(
                            "mma.sync.aligned.m16n8k16.row.col.f32.f16.f16.f32 "
                            "{%0,%1,%2,%3}, {%4,%5,%6,%7}, {%8,%9}, {%0,%1,%2,%3};"
                            : "+f"(acc[mt][2*j][0]), "+f"(acc[mt][2*j][1]),
                              "+f"(acc[mt][2*j][2]), "+f"(acc[mt][2*j][3])
                            : "r"(a[mt][0]), "r"(a[mt][1]), "r"(a[mt][2]), "r"(a[mt][3]),
                              "r"(b0), "r"(b1));
                        asm volatile(
                            "mma.sync.aligned.m16n8k16.row.col.f32.f16.f16.f32 "
                            "{%0,%1,%2,%3}, {%4,%5,%6,%7}, {%8,%9}, {%0,%1,%2,%3};"
                            : "+f"(acc[mt][2*j+1][0]), "+f"(acc[mt][2*j+1][1]),
                              "+f"(acc[mt][2*j+1][2]), "+f"(acc[mt][2*j+1][3])
                            : "r"(a[mt][0]), "r"(a[mt][1]), "r"(a[mt][2]), "r"(a[mt][3]),
                              "r"(b2), "r"(b3));
                    }
                }
            }
            if (kt < 7) {
                const int nxt = (kt + 1) & 1;
                #pragma unroll
                for (int cc = 0; cc < 4; cc++) {
                    int c = cc * 512 + tid;
                    int n = c >> 3, u = c & 7;
                    *(uint4*)(smem + 131072 + nxt * 32768 + n * 128
                              + ((u ^ (n & 7)) << 4)) = wreg[cc];
                }
                __syncthreads();
            }
        }

        // ---- Epilogue: bias + SiLU + store ----
        #pragma unroll
        for (int mt = 0; mt < 2; mt++) {
            int row = mbase + mw + mt * 16 + (lane >> 2);
            #pragma unroll
            for (int nt = 0; nt < 8; nt++) {
                int col = nchunk + nw + nt * 8 + (lane & 3) * 2;
                float2 bv = *(const float2*)(bias + col);
                float v0 = acc[mt][nt][0] + bv.x;
                float v1 = acc[mt][nt][1] + bv.y;
                float v2 = acc[mt][nt][2] + bv.x;
                float v3 = acc[mt][nt][3] + bv.y;
                v0 = v0 / (1.0f + __expf(-v0));
                v1 = v1 / (1.0f + __expf(-v1));
                v2 = v2 / (1.0f + __expf(-v2));
                v3 = v3 / (1.0f + __expf(-v3));
                *(float2*)(out + (size_t)row * 1024 + col)       = make_float2(v0, v1);
                *(float2*)(out + (size_t)(row + 8) * 1024 + col) = make_float2(v2, v3);
            }
        }
        // Next nb's prologue writes buf0; buf0 was last read at kt==6 (pre-sync). Safe.
    }
}

// ---------------------------------------------------------------------------
extern "C" void kernel_launch(void* const* d_in, const int* in_sizes, int n_in,
                              void* d_out, int out_size) {
    const float* T = (const float*)d_in[0];
    const float* W = (const float*)d_in[1];
    const float* b = (const float*)d_in[2];
    float* out = (float*)d_out;

    prep_kernel<<<(TOUT * TDIM + 255) / 256, 256>>>(W);

    cudaFuncSetAttribute(temb_main, cudaFuncAttributeMaxDynamicSharedMemorySize, 196608);
    temb_main<<<TBATCH / 128, 512, 196608>>>(T, b, out);
}

// round 6
// speedup vs baseline: 1.1045x; 1.1045x over previous
#include <cuda_runtime.h>
#include <cuda_fp16.h>
#include <math.h>
#include <stdint.h>

#define TDIM 512
#define TOUT 1024
#define TBATCH 65536

// Scratch: W converted to fp16 (1MB) + inv_freq table (device globals = legal scratch).
__device__ __half g_W16[TOUT * TDIM];
__device__ float  g_invf[TDIM];

// Elements per 256-row x 512-col W chunk (g_W16 is __half*, arithmetic in ELEMENTS).
#define W_CHUNK_ELEMS 131072

// ---------------------------------------------------------------------------
// Prep: W fp32 -> fp16; inv_freq matching reference fp32 intermediates.
// ---------------------------------------------------------------------------
__global__ void prep_kernel(const float* __restrict__ W) {
    int idx = blockIdx.x * blockDim.x + threadIdx.x;
    if (idx < TOUT * TDIM)
        g_W16[idx] = __float2half_rn(W[idx]);
    if (idx < TDIM) {
        float a  = (2.0f * (float)idx) / 512.0f;
        float xf = __fmul_rn(a, 9.210340371976184f);
        g_invf[idx] = (float)exp(-(double)xf);
    }
}

// ---------------------------------------------------------------------------
// Accurate sin/cos for x in [0, ~1024] rad. odd=0 -> sin, odd=1 -> cos.
// ---------------------------------------------------------------------------
__device__ __forceinline__ float sincos_sel(float x, int odd) {
    float j  = __fmaf_rn(x, 0.63661977236758134f, 12582912.0f);
    int   qi = __float_as_int(j);
    float jf = __fadd_rn(j, -12582912.0f);
    float r  = __fmaf_rn(jf, -1.57079601e+00f, x);
    r        = __fmaf_rn(jf, -3.13916473e-07f, r);
    r        = __fmaf_rn(jf, -5.39030253e-15f, r);
    float r2 = __fmul_rn(r, r);
    float ps = __fmaf_rn(2.75573192e-6f, r2, -1.98412698e-4f);
    ps = __fmaf_rn(ps, r2, 8.33333333e-3f);
    ps = __fmaf_rn(ps, r2, -1.66666667e-1f);
    float sp = __fmaf_rn(ps * r2, r, r);
    float pc = __fmaf_rn(2.48015873e-5f, r2, -1.38888889e-3f);
    pc = __fmaf_rn(pc, r2, 4.16666667e-2f);
    pc = __fmaf_rn(pc, r2, -5.0e-1f);
    float cp = __fmaf_rn(pc, r2, 1.0f);
    int qq = qi + odd;
    float v = (qq & 1) ? cp : sp;
    return (qq & 2) ? -v : v;
}

#define CP_ASYNC16(dst, src) \
    asm volatile("cp.async.cg.shared.global [%0], [%1], 16;" :: "r"(dst), "l"(src))
#define CP_COMMIT()  asm volatile("cp.async.commit_group;")
#define CP_WAIT1()   asm volatile("cp.async.wait_group 1;")
#define CP_WAIT0()   asm volatile("cp.async.wait_group 0;")

// SMEM: A emb [128x512] fp16 swizzled = 131072 B at 0
//       B ring: 3 stages x [256n x 64k] fp16 swizzled = 3 x 32768 B at 131072
#define A_OFF 0
#define B_OFF 131072
#define B_STAGE 32768
#define SMEM_TOTAL 229376

__device__ __forceinline__ void ldmat_a(uint32_t addr, uint32_t* r) {
    asm volatile("ldmatrix.sync.aligned.m8n8.x4.shared.b16 {%0,%1,%2,%3}, [%4];"
                 : "=r"(r[0]), "=r"(r[1]), "=r"(r[2]), "=r"(r[3]) : "r"(addr));
}

__global__ void __launch_bounds__(512, 1) temb_main(
    const float* __restrict__ T,
    const float* __restrict__ bias,
    float* __restrict__ out)
{
    extern __shared__ char smem[];
    const int tid = threadIdx.x;
    const int mbase = blockIdx.x * 128;
    uint32_t sbase;
    asm("{ .reg .u64 t; cvta.to.shared.u64 t, %1; cvt.u32.u64 %0, t; }"
        : "=r"(sbase) : "l"(smem));

    // ---- cp.async per-thread offsets (4 x 16B per thread per stage) ----
    uint32_t cp_dst[4];
    uint32_t cp_src[4];
    #pragma unroll
    for (int i = 0; i < 4; i++) {
        int e = i * 512 + tid;          // 16B chunk id within stage [0,2048)
        int n = e >> 3, u = e & 7;
        cp_dst[i] = (uint32_t)(n * 128 + ((u ^ (n & 7)) << 4));
        cp_src[i] = (uint32_t)(n * 512 + u * 8);  // element offset in W row-block
    }

    // ---- Prologue: start B pipeline for stages 0,1 ----
    #pragma unroll
    for (int s = 0; s < 2; s++) {
        const __half* sb = g_W16 + (size_t)(s >> 3) * W_CHUNK_ELEMS + (s & 7) * 64;
        uint32_t db = sbase + B_OFF + (uint32_t)(s % 3) * B_STAGE;
        #pragma unroll
        for (int i = 0; i < 4; i++)
            CP_ASYNC16(db + cp_dst[i], (const void*)(sb + cp_src[i]));
        CP_COMMIT();
    }

    // ---- Phase 1: embedding -> A smem (swizzled fp16), overlaps cp.async ----
    for (int p = tid; p < 128 * 256; p += 512) {
        int row = p >> 8;
        int c2  = (p & 255) * 2;
        float t  = __ldg(&T[mbase + row]);
        float e0 = sincos_sel(__fmul_rn(t, g_invf[c2]), 0);
        float e1 = sincos_sel(__fmul_rn(t, g_invf[c2 + 1]), 1);
        __half2 h = __floats2half2_rn(e0, e1);
        int u = c2 >> 3;
        *(__half2*)(smem + row * 1024 + ((u ^ (row & 7)) << 4) + ((c2 & 7) << 1)) = h;
    }

    const int lane = tid & 31;
    const int w    = tid >> 5;
    const int mw   = (w >> 2) * 32;
    const int nw   = (w & 3) * 64;
    const int arow0 = mw + ((lane >> 3) & 1) * 8 + (lane & 7);
    const int a_c8  = lane >> 4;
    const int bn0   = (lane & 7) + ((lane >> 4) << 3);
    const int b_k8  = (lane >> 3) & 1;

    // Precomputed A smem addresses for the two m-tiles (k-unit varies per kk).
    const uint32_t a_addr0 = sbase + (uint32_t)arow0 * 1024u;
    const uint32_t a_addr1 = sbase + (uint32_t)(arow0 + 16) * 1024u;
    const uint32_t a_x0 = (uint32_t)(arow0 & 7);
    const uint32_t a_x1 = (uint32_t)((arow0 + 16) & 7);

    float acc[2][8][4];

    for (int s = 0; s < 32; s++) {
        const int kt = s & 7, nb = s >> 3, buf = s % 3;

        if (kt == 0) {
            #pragma unroll
            for (int mt = 0; mt < 2; mt++)
                #pragma unroll
                for (int nt = 0; nt < 8; nt++) {
                    acc[mt][nt][0] = 0.f; acc[mt][nt][1] = 0.f;
                    acc[mt][nt][2] = 0.f; acc[mt][nt][3] = 0.f;
                }
        }

        // stage s complete (leave newest group in flight), then publish CTA-wide
        if (s == 31) { CP_WAIT0(); } else { CP_WAIT1(); }
        __syncthreads();

        // issue stage s+2 (buffer (s+2)%3 == (s-1)%3, free after the barrier)
        if (s + 2 < 32) {
            int s2 = s + 2;
            const __half* sb = g_W16 + (size_t)(s2 >> 3) * W_CHUNK_ELEMS + (s2 & 7) * 64;
            uint32_t db = sbase + B_OFF + (uint32_t)(s2 % 3) * B_STAGE;
            #pragma unroll
            for (int i = 0; i < 4; i++)
                CP_ASYNC16(db + cp_dst[i], (const void*)(sb + cp_src[i]));
            CP_COMMIT();
        }

        // ---- MMA over this 64-wide k-tile, 1-deep A-fragment pipeline ----
        const uint32_t wsm = sbase + B_OFF + (uint32_t)buf * B_STAGE;

        uint32_t a_cur[2][4], a_nxt[2][4];
        {
            uint32_t u0 = (uint32_t)(kt * 8 + a_c8);
            ldmat_a(a_addr0 + ((u0 ^ a_x0) << 4), a_cur[0]);
            ldmat_a(a_addr1 + ((u0 ^ a_x1) << 4), a_cur[1]);
        }

        #pragma unroll
        for (int kk = 0; kk < 4; kk++) {
            if (kk < 3) {
                uint32_t un = (uint32_t)(kt * 8 + (kk + 1) * 2 + a_c8);
                ldmat_a(a_addr0 + ((un ^ a_x0) << 4), a_nxt[0]);
                ldmat_a(a_addr1 + ((un ^ a_x1) << 4), a_nxt[1]);
            }
            #pragma unroll
            for (int j = 0; j < 4; j++) {
                uint32_t b0, b1, b2, b3;
                int n = nw + j * 16 + bn0;
                int u = kk * 2 + b_k8;
                uint32_t addr = wsm + n * 128 + ((u ^ (n & 7)) << 4);
                asm volatile(
                    "ldmatrix.sync.aligned.m8n8.x4.shared.b16 {%0,%1,%2,%3}, [%4];"
                    : "=r"(b0), "=r"(b1), "=r"(b2), "=r"(b3) : "r"(addr));
                #pragma unroll
                for (int mt = 0; mt < 2; mt++) {
                    asm volatile(
                        "mma.sync.aligned.m16n8k16.row.col.f32.f16.f16.f32 "
                        "{%0,%1,%2,%3}, {%4,%5,%6,%7}, {%8,%9}, {%0,%1,%2,%3};"
                        : "+f"(acc[mt][2*j][0]), "+f"(acc[mt][2*j][1]),
                          "+f"(acc[mt][2*j][2]), "+f"(acc[mt][2*j][3])
                        : "r"(a_cur[mt][0]), "r"(a_cur[mt][1]),
                          "r"(a_cur[mt][2]), "r"(a_cur[mt][3]),
                          "r"(b0), "r"(b1));
                    asm volatile(
                        "mma.sync.aligned.m16n8k16.row.col.f32.f16.f16.f32 "
                        "{%0,%1,%2,%3}, {%4,%5,%6,%7}, {%8,%9}, {%0,%1,%2,%3};"
                        : "+f"(acc[mt][2*j+1][0]), "+f"(acc[mt][2*j+1][1]),
                          "+f"(acc[mt][2*j+1][2]), "+f"(acc[mt][2*j+1][3])
                        : "r"(a_cur[mt][0]), "r"(a_cur[mt][1]),
                          "r"(a_cur[mt][2]), "r"(a_cur[mt][3]),
                          "r"(b2), "r"(b3));
                }
            }
            if (kk < 3) {
                #pragma unroll
                for (int mt = 0; mt < 2; mt++)
                    #pragma unroll
                    for (int q = 0; q < 4; q++)
                        a_cur[mt][q] = a_nxt[mt][q];
            }
        }

        // ---- Epilogue for finished 256-col chunk (overlaps in-flight cp.async) ----
        if (kt == 7) {
            const int nchunk = nb * 256;
            #pragma unroll
            for (int mt = 0; mt < 2; mt++) {
                int row = mbase + mw + mt * 16 + (lane >> 2);
                #pragma unroll
                for (int nt = 0; nt < 8; nt++) {
                    int col = nchunk + nw + nt * 8 + (lane & 3) * 2;
                    float2 bv = *(const float2*)(bias + col);
                    float v0 = acc[mt][nt][0] + bv.x;
                    float v1 = acc[mt][nt][1] + bv.y;
                    float v2 = acc[mt][nt][2] + bv.x;
                    float v3 = acc[mt][nt][3] + bv.y;
                    v0 = v0 / (1.0f + __expf(-v0));
                    v1 = v1 / (1.0f + __expf(-v1));
                    v2 = v2 / (1.0f + __expf(-v2));
                    v3 = v3 / (1.0f + __expf(-v3));
                    *(float2*)(out + (size_t)row * 1024 + col)       = make_float2(v0, v1);
                    *(float2*)(out + (size_t)(row + 8) * 1024 + col) = make_float2(v2, v3);
                }
            }
        }
    }
}

// ---------------------------------------------------------------------------
extern "C" void kernel_launch(void* const* d_in, const int* in_sizes, int n_in,
                              void* d_out, int out_size) {
    const float* T = (const float*)d_in[0];
    const float* W = (const float*)d_in[1];
    const float* b = (const float*)d_in[2];
    float* out = (float*)d_out;

    prep_kernel<<<(TOUT * TDIM + 255) / 256, 256>>>(W);

    cudaFuncSetAttribute(temb_main, cudaFuncAttributeMaxDynamicSharedMemorySize, SMEM_TOTAL);
    temb_main<<<TBATCH / 128, 512, SMEM_TOTAL>>>(T, b, out);
}

// round 7
// speedup vs baseline: 1.1310x; 1.0240x over previous
#include <cuda_runtime.h>
#include <cuda_fp16.h>
#include <math.h>
#include <stdint.h>

#define TDIM 512
#define TOUT 1024
#define TBATCH 65536

// Scratch: W converted to fp16 (1MB) + inv_freq table (device globals = legal scratch).
__device__ __half g_W16[TOUT * TDIM];
__device__ float  g_invf[TDIM];

// Elements per 256-row x 512-col W chunk (g_W16 is __half*, arithmetic in ELEMENTS).
#define W_CHUNK_ELEMS 131072

// ---------------------------------------------------------------------------
// Prep: W fp32 -> fp16; inv_freq matching reference fp32 intermediates.
// ---------------------------------------------------------------------------
__global__ void prep_kernel(const float* __restrict__ W) {
    int idx = blockIdx.x * blockDim.x + threadIdx.x;
    if (idx < TOUT * TDIM)
        g_W16[idx] = __float2half_rn(W[idx]);
    if (idx < TDIM) {
        float a  = (2.0f * (float)idx) / 512.0f;
        float xf = __fmul_rn(a, 9.210340371976184f);
        g_invf[idx] = (float)exp(-(double)xf);
    }
}

// ---------------------------------------------------------------------------
// Accurate sin/cos for x in [0, ~1024] rad. odd=0 -> sin, odd=1 -> cos.
// ---------------------------------------------------------------------------
__device__ __forceinline__ float sincos_sel(float x, int odd) {
    float j  = __fmaf_rn(x, 0.63661977236758134f, 12582912.0f);
    int   qi = __float_as_int(j);
    float jf = __fadd_rn(j, -12582912.0f);
    float r  = __fmaf_rn(jf, -1.57079601e+00f, x);
    r        = __fmaf_rn(jf, -3.13916473e-07f, r);
    r        = __fmaf_rn(jf, -5.39030253e-15f, r);
    float r2 = __fmul_rn(r, r);
    float ps = __fmaf_rn(2.75573192e-6f, r2, -1.98412698e-4f);
    ps = __fmaf_rn(ps, r2, 8.33333333e-3f);
    ps = __fmaf_rn(ps, r2, -1.66666667e-1f);
    float sp = __fmaf_rn(ps * r2, r, r);
    float pc = __fmaf_rn(2.48015873e-5f, r2, -1.38888889e-3f);
    pc = __fmaf_rn(pc, r2, 4.16666667e-2f);
    pc = __fmaf_rn(pc, r2, -5.0e-1f);
    float cp = __fmaf_rn(pc, r2, 1.0f);
    int qq = qi + odd;
    float v = (qq & 1) ? cp : sp;
    return (qq & 2) ? -v : v;
}

#define CP_ASYNC16(dst, src) \
    asm volatile("cp.async.cg.shared.global [%0], [%1], 16;" :: "r"(dst), "l"(src))
#define CP_COMMIT()  asm volatile("cp.async.commit_group;")
#define CP_WAIT1()   asm volatile("cp.async.wait_group 1;")
#define CP_WAIT0()   asm volatile("cp.async.wait_group 0;")

// SMEM: A emb [128x512] fp16 swizzled = 131072 B at 0
//       B ring: 3 stages x [256n x 64k] fp16 swizzled = 3 x 32768 B at 131072
#define A_OFF 0
#define B_OFF 131072
#define B_STAGE 32768
#define SMEM_TOTAL 229376

__device__ __forceinline__ void ldmat4(uint32_t addr, uint32_t* r) {
    asm volatile("ldmatrix.sync.aligned.m8n8.x4.shared.b16 {%0,%1,%2,%3}, [%4];"
                 : "=r"(r[0]), "=r"(r[1]), "=r"(r[2]), "=r"(r[3]) : "r"(addr));
}

__global__ void __launch_bounds__(1024, 1) temb_main(
    const float* __restrict__ T,
    const float* __restrict__ bias,
    float* __restrict__ out)
{
    extern __shared__ char smem[];
    const int tid = threadIdx.x;
    const int mbase = blockIdx.x * 128;
    uint32_t sbase;
    asm("{ .reg .u64 t; cvta.to.shared.u64 t, %1; cvt.u32.u64 %0, t; }"
        : "=r"(sbase) : "l"(smem));

    // ---- cp.async per-thread offsets (2 x 16B per thread per stage) ----
    uint32_t cp_dst[2], cp_src[2];
    #pragma unroll
    for (int i = 0; i < 2; i++) {
        int e = i * 1024 + tid;         // 16B chunk id within stage [0,2048)
        int n = e >> 3, u = e & 7;
        cp_dst[i] = (uint32_t)(n * 128 + ((u ^ (n & 7)) << 4));
        cp_src[i] = (uint32_t)(n * 512 + u * 8);  // element offset in W row-block
    }

    // ---- Prologue: start B pipeline for stages 0,1 ----
    #pragma unroll
    for (int s = 0; s < 2; s++) {
        const __half* sb = g_W16 + (size_t)(s >> 3) * W_CHUNK_ELEMS + (s & 7) * 64;
        uint32_t db = sbase + B_OFF + (uint32_t)(s % 3) * B_STAGE;
        #pragma unroll
        for (int i = 0; i < 2; i++)
            CP_ASYNC16(db + cp_dst[i], (const void*)(sb + cp_src[i]));
        CP_COMMIT();
    }

    // ---- Phase 1: embedding -> A smem (swizzled fp16), overlaps cp.async ----
    for (int p = tid; p < 128 * 256; p += 1024) {
        int row = p >> 8;
        int c2  = (p & 255) * 2;
        float t  = __ldg(&T[mbase + row]);
        float e0 = sincos_sel(__fmul_rn(t, g_invf[c2]), 0);
        float e1 = sincos_sel(__fmul_rn(t, g_invf[c2 + 1]), 1);
        __half2 h = __floats2half2_rn(e0, e1);
        int u = c2 >> 3;
        *(__half2*)(smem + row * 1024 + ((u ^ (row & 7)) << 4) + ((c2 & 7) << 1)) = h;
    }

    // ---- Warp tiling: 32 warps = 4M x 8N, warp tile 32M x 32N ----
    const int lane = tid & 31;
    const int w    = tid >> 5;
    const int mw   = (w & 3) * 32;       // warp M offset (0..96)
    const int nwg  = (w >> 2) * 32;      // warp N offset within 256-chunk (0..224)
    const int arow0 = mw + ((lane >> 3) & 1) * 8 + (lane & 7);
    const int a_c8  = lane >> 4;
    const int bn0   = (lane & 7) + ((lane >> 4) << 3);
    const int b_k8  = (lane >> 3) & 1;

    const uint32_t a_addr0 = sbase + (uint32_t)arow0 * 1024u;
    const uint32_t a_addr1 = sbase + (uint32_t)(arow0 + 16) * 1024u;
    const uint32_t a_x0 = (uint32_t)(arow0 & 7);
    const uint32_t a_x1 = (uint32_t)((arow0 + 16) & 7);

    float acc[2][4][4];   // [mt][n8-tile][quad] = 32 regs

    for (int s = 0; s < 32; s++) {
        const int kt = s & 7, nb = s >> 3, buf = s % 3;

        if (kt == 0) {
            #pragma unroll
            for (int mt = 0; mt < 2; mt++)
                #pragma unroll
                for (int nt = 0; nt < 4; nt++) {
                    acc[mt][nt][0] = 0.f; acc[mt][nt][1] = 0.f;
                    acc[mt][nt][2] = 0.f; acc[mt][nt][3] = 0.f;
                }
        }

        // stage s complete (leave newest group in flight), then publish CTA-wide
        if (s == 31) { CP_WAIT0(); } else { CP_WAIT1(); }
        __syncthreads();

        // issue stage s+2 (buffer (s+2)%3 == (s-1)%3, free after the barrier)
        if (s + 2 < 32) {
            int s2 = s + 2;
            const __half* sb = g_W16 + (size_t)(s2 >> 3) * W_CHUNK_ELEMS + (s2 & 7) * 64;
            uint32_t db = sbase + B_OFF + (uint32_t)(s2 % 3) * B_STAGE;
            #pragma unroll
            for (int i = 0; i < 2; i++)
                CP_ASYNC16(db + cp_dst[i], (const void*)(sb + cp_src[i]));
            CP_COMMIT();
        }

        // ---- MMA over this 64-wide k-tile ----
        const uint32_t wsm = sbase + B_OFF + (uint32_t)buf * B_STAGE;
        #pragma unroll
        for (int kk = 0; kk < 4; kk++) {
            uint32_t a[2][4];
            {
                uint32_t u0 = (uint32_t)(kt * 8 + kk * 2 + a_c8);
                ldmat4(a_addr0 + ((u0 ^ a_x0) << 4), a[0]);
                ldmat4(a_addr1 + ((u0 ^ a_x1) << 4), a[1]);
            }
            #pragma unroll
            for (int j = 0; j < 2; j++) {
                uint32_t b[4];
                int n = nwg + j * 16 + bn0;
                int u = kk * 2 + b_k8;
                ldmat4(wsm + n * 128 + ((u ^ (n & 7)) << 4), b);
                #pragma unroll
                for (int mt = 0; mt < 2; mt++) {
                    asm volatile(
                        "mma.sync.aligned.m16n8k16.row.col.f32.f16.f16.f32 "
                        "{%0,%1,%2,%3}, {%4,%5,%6,%7}, {%8,%9}, {%0,%1,%2,%3};"
                        : "+f"(acc[mt][2*j][0]), "+f"(acc[mt][2*j][1]),
                          "+f"(acc[mt][2*j][2]), "+f"(acc[mt][2*j][3])
                        : "r"(a[mt][0]), "r"(a[mt][1]), "r"(a[mt][2]), "r"(a[mt][3]),
                          "r"(b[0]), "r"(b[1]));
                    asm volatile(
                        "mma.sync.aligned.m16n8k16.row.col.f32.f16.f16.f32 "
                        "{%0,%1,%2,%3}, {%4,%5,%6,%7}, {%8,%9}, {%0,%1,%2,%3};"
                        : "+f"(acc[mt][2*j+1][0]), "+f"(acc[mt][2*j+1][1]),
                          "+f"(acc[mt][2*j+1][2]), "+f"(acc[mt][2*j+1][3])
                        : "r"(a[mt][0]), "r"(a[mt][1]), "r"(a[mt][2]), "r"(a[mt][3]),
                          "r"(b[2]), "r"(b[3]));
                }
            }
        }

        // ---- Epilogue for finished 256-col chunk (overlaps in-flight cp.async) ----
        if (kt == 7) {
            const int nchunk = nb * 256;
            #pragma unroll
            for (int mt = 0; mt < 2; mt++) {
                int row = mbase + mw + mt * 16 + (lane >> 2);
                #pragma unroll
                for (int nt = 0; nt < 4; nt++) {
                    int col = nchunk + nwg + nt * 8 + (lane & 3) * 2;
                    float2 bv = *(const float2*)(bias + col);
                    float v0 = acc[mt][nt][0] + bv.x;
                    float v1 = acc[mt][nt][1] + bv.y;
                    float v2 = acc[mt][nt][2] + bv.x;
                    float v3 = acc[mt][nt][3] + bv.y;
                    v0 = v0 / (1.0f + __expf(-v0));
                    v1 = v1 / (1.0f + __expf(-v1));
                    v2 = v2 / (1.0f + __expf(-v2));
                    v3 = v3 / (1.0f + __expf(-v3));
                    *(float2*)(out + (size_t)row * 1024 + col)       = make_float2(v0, v1);
                    *(float2*)(out + (size_t)(row + 8) * 1024 + col) = make_float2(v2, v3);
                }
            }
        }
    }
}

// ---------------------------------------------------------------------------
extern "C" void kernel_launch(void* const* d_in, const int* in_sizes, int n_in,
                              void* d_out, int out_size) {
    const float* T = (const float*)d_in[0];
    const float* W = (const float*)d_in[1];
    const float* b = (const float*)d_in[2];
    float* out = (float*)d_out;

    prep_kernel<<<(TOUT * TDIM + 255) / 256, 256>>>(W);

    cudaFuncSetAttribute(temb_main, cudaFuncAttributeMaxDynamicSharedMemorySize, SMEM_TOTAL);
    temb_main<<<TBATCH / 128, 1024, SMEM_TOTAL>>>(T, b, out);
}